// round 14
// baseline (speedup 1.0000x reference)
#include <cuda_runtime.h>

typedef unsigned long long u64;

#define TT 50
#define EE 10
#define BB 65536

__device__ __forceinline__ u64 ffma2(u64 a, u64 b, u64 c){
    u64 d; asm("fma.rn.f32x2 %0, %1, %2, %3;" : "=l"(d) : "l"(a), "l"(b), "l"(c)); return d;
}
__device__ __forceinline__ u64 splat2(float v){
    u64 r; asm("mov.b64 %0, {%1, %1};" : "=l"(r) : "f"(v)); return r;
}
__device__ __forceinline__ void unpack2(u64 v, float& lo, float& hi){
    asm("mov.b64 {%0, %1}, %2;" : "=f"(lo), "=f"(hi) : "l"(v));
}
__device__ __forceinline__ float sigmoidf_fast(float v){
    return __fdividef(1.0f, 1.0f + __expf(-v));
}
__device__ __forceinline__ float tanhf_fast(float v){
    return 1.0f - __fdividef(2.0f, __expf(2.0f * v) + 1.0f);
}

#define NTH 64
#define RSTRIDE 42   // floats per batch row in staging: [0..19]=x(t0,t1), [20..39]=a(t0,t1), pad 2

__global__ void __launch_bounds__(NTH, 7) augru_kernel(
    const float* __restrict__ X, const float* __restrict__ Aat,
    const float* __restrict__ h0,
    const float* __restrict__ Wi_r, const float* __restrict__ bi_r,
    const float* __restrict__ Wh_r, const float* __restrict__ Ws_r, const float* __restrict__ bs_r,
    const float* __restrict__ Wi_z, const float* __restrict__ bi_z,
    const float* __restrict__ Wh_z, const float* __restrict__ Ws_z, const float* __restrict__ bs_z,
    const float* __restrict__ Wi_h, const float* __restrict__ bi_h,
    const float* __restrict__ Wh_h, const float* __restrict__ Wt_h, const float* __restrict__ bt_h,
    float* __restrict__ out)
{
    // Packed fused weights (co-consumed rows contiguous):
    //  sWX[i][0..9]=(Wi_r@Ws_r)[i], [10..19]=(Wi_z@Ws_z)[i], [20..29]=(Wi_h@Wt_h)[i]
    //  sWH[i][0..9]=(Wh_r@Ws_r)[i], [10..19]=(Wh_z@Ws_z)[i]
    //  sWG[i][0..9]=(Wh_h@Wt_h)[i]
    __shared__ __align__(16) float sWX[EE][32];
    __shared__ __align__(16) float sWH[EE][24];
    __shared__ __align__(16) float sWG[EE][16];
    __shared__ __align__(16) float sB[3][16];
    __shared__ float sH0[16];
    __shared__ __align__(16) float sIn[2][NTH * RSTRIDE];   // 2 x 10752 B

    {
        for (int idx = threadIdx.x; idx < EE * 32; idx += NTH){
            int i = idx >> 5, j = idx & 31;
            float v = 0.0f;
            if (j < 30){
                int m = j / 10, jj = j % 10;
                const float* a  = (m==0) ? Wi_r : (m==1) ? Wi_z : Wi_h;
                const float* b2 = (m==0) ? Ws_r : (m==1) ? Ws_z : Wt_h;
                #pragma unroll
                for (int k = 0; k < EE; k++) v = fmaf(a[i*EE + k], b2[k*EE + jj], v);
            }
            sWX[i][j] = v;
        }
        for (int idx = threadIdx.x; idx < EE * 24; idx += NTH){
            int i = idx / 24, j = idx % 24;
            float v = 0.0f;
            if (j < 20){
                int m = j / 10, jj = j % 10;
                const float* a  = (m==0) ? Wh_r : Wh_z;
                const float* b2 = (m==0) ? Ws_r : Ws_z;
                #pragma unroll
                for (int k = 0; k < EE; k++) v = fmaf(a[i*EE + k], b2[k*EE + jj], v);
            }
            sWH[i][j] = v;
        }
        for (int idx = threadIdx.x; idx < EE * 16; idx += NTH){
            int i = idx >> 4, j = idx & 15;
            float v = 0.0f;
            if (j < EE){
                #pragma unroll
                for (int k = 0; k < EE; k++) v = fmaf(Wh_h[i*EE + k], Wt_h[k*EE + j], v);
            }
            sWG[i][j] = v;
        }
        for (int idx = threadIdx.x; idx < 48; idx += NTH){
            int g = idx >> 4, j = idx & 15;
            float v = 0.0f;
            if (j < EE){
                const float* bi = (g==0) ? bi_r : (g==1) ? bi_z : bi_h;
                const float* bs = (g==0) ? bs_r : (g==1) ? bs_z : bt_h;
                const float* Wg = (g==0) ? Ws_r : (g==1) ? Ws_z : Wt_h;
                v = bs[j];
                #pragma unroll
                for (int k = 0; k < EE; k++) v = fmaf(bi[k], Wg[k*EE + j], v);
            }
            sB[g][j] = v;
        }
        if (threadIdx.x < 16) sH0[threadIdx.x] = (threadIdx.x < EE) ? h0[threadIdx.x] : 0.0f;
    }

    const int tid = threadIdx.x;
    const long b0 = (long)blockIdx.x * NTH;

    // 2-step chunk staging: per chunk c, CTA needs NTH batches x 80 B from X and A.
    // Slot k (k=0..4): idx = tid+64k -> bb = idx/5, pp = idx%5 (float4 part).
    // Global float4 index for chunk c: (b0+bb)*125 + c*5 + pp.
    const float4* X4 = (const float4*)X;
    const float4* A4 = (const float4*)Aat;
    long gbase[5]; int sbase[5];
    #pragma unroll
    for (int k = 0; k < 5; k++){
        int idx = tid + NTH*k;
        int bb = idx / 5, pp = idx % 5;
        gbase[k] = (b0 + bb) * 125 + pp;
        sbase[k] = bb * RSTRIDE + 4*pp;
    }

    // stage chunk 0
    {
        float4 vx[5], va[5];
        #pragma unroll
        for (int k = 0; k < 5; k++){ vx[k] = X4[gbase[k]]; va[k] = A4[gbase[k]]; }
        #pragma unroll
        for (int k = 0; k < 5; k++){
            float* d = &sIn[0][sbase[k]];
            *(float2*)(d)      = make_float2(vx[k].x, vx[k].y);
            *(float2*)(d + 2)  = make_float2(vx[k].z, vx[k].w);
            *(float2*)(d + 20) = make_float2(va[k].x, va[k].y);
            *(float2*)(d + 22) = make_float2(va[k].z, va[k].w);
        }
    }
    __syncthreads();

    float h[EE];
    #pragma unroll
    for (int j = 0; j < EE; j++) h[j] = sH0[j];

    #pragma unroll 1
    for (int c = 0; c < TT/2; c++){
        // prefetch chunk c+1 (latency hidden by half-0 compute)
        float4 vx[5], va[5];
        if (c + 1 < TT/2){
            #pragma unroll
            for (int k = 0; k < 5; k++){
                vx[k] = X4[gbase[k] + (c+1)*5];
                va[k] = A4[gbase[k] + (c+1)*5];
            }
        }

        const float* myrow = &sIn[c & 1][tid * RSTRIDE];

        #pragma unroll
        for (int half = 0; half < 2; half++){
            const float* myx = myrow + half*10;
            const float* mya = myrow + 20 + half*10;

            float x[EE];
            #pragma unroll
            for (int p = 0; p < 5; p++){
                float2 v = *(const float2*)(myx + 2*p);
                x[2*p] = v.x; x[2*p+1] = v.y;
            }

            u64 accR[5], accZ[5], accH[5];
            #pragma unroll
            for (int p = 0; p < 5; p++){
                accR[p] = *(const u64*)&sB[0][2*p];
                accZ[p] = *(const u64*)&sB[1][2*p];
                accH[p] = *(const u64*)&sB[2][2*p];
            }

            // x contributions: packed 32-float row feeds all three gates
            #pragma unroll
            for (int i = 0; i < EE; i++){
                u64 sx = splat2(x[i]);
                const ulonglong2* w = (const ulonglong2*)&sWX[i][0];
                ulonglong2 w0 = w[0], w1 = w[1], w2 = w[2], w3 = w[3];
                accR[0] = ffma2(sx, w0.x, accR[0]);
                accR[1] = ffma2(sx, w0.y, accR[1]);
                accR[2] = ffma2(sx, w1.x, accR[2]);
                accR[3] = ffma2(sx, w1.y, accR[3]);
                accR[4] = ffma2(sx, w2.x, accR[4]);
                accZ[0] = ffma2(sx, w2.y, accZ[0]);
                accZ[1] = ffma2(sx, w3.x, accZ[1]);
                accZ[2] = ffma2(sx, w3.y, accZ[2]);
                ulonglong2 w4 = w[4], w5 = w[5], w6 = w[6], w7 = w[7];
                accZ[3] = ffma2(sx, w4.x, accZ[3]);
                accZ[4] = ffma2(sx, w4.y, accZ[4]);
                accH[0] = ffma2(sx, w5.x, accH[0]);
                accH[1] = ffma2(sx, w5.y, accH[1]);
                accH[2] = ffma2(sx, w6.x, accH[2]);
                accH[3] = ffma2(sx, w6.y, accH[3]);
                accH[4] = ffma2(sx, w7.x, accH[4]);
            }
            // h contributions: packed 24-float row feeds r and z
            #pragma unroll
            for (int i = 0; i < EE; i++){
                u64 sh = splat2(h[i]);
                const ulonglong2* w = (const ulonglong2*)&sWH[i][0];
                ulonglong2 w0 = w[0], w1 = w[1];
                u64 w2x = ((const u64*)&sWH[i][0])[4];
                accR[0] = ffma2(sh, w0.x, accR[0]);
                accR[1] = ffma2(sh, w0.y, accR[1]);
                accR[2] = ffma2(sh, w1.x, accR[2]);
                accR[3] = ffma2(sh, w1.y, accR[3]);
                accR[4] = ffma2(sh, w2x,  accR[4]);
                ulonglong2 w2 = ((const ulonglong2*)&sWH[i][0])[2];
                ulonglong2 w3 = w[3], w4 = w[4];
                accZ[0] = ffma2(sh, w2.y, accZ[0]);
                accZ[1] = ffma2(sh, w3.x, accZ[1]);
                accZ[2] = ffma2(sh, w3.y, accZ[2]);
                accZ[3] = ffma2(sh, w4.x, accZ[3]);
                accZ[4] = ffma2(sh, w4.y, accZ[4]);
            }

            float r[EE], g[EE];
            #pragma unroll
            for (int p = 0; p < 5; p++){
                float r0, r1; unpack2(accR[p], r0, r1);
                r[2*p]   = sigmoidf_fast(r0);
                r[2*p+1] = sigmoidf_fast(r1);
                float z0, z1; unpack2(accZ[p], z0, z1);
                g[2*p]   = h[2*p]   * sigmoidf_fast(z0);
                g[2*p+1] = h[2*p+1] * sigmoidf_fast(z1);
            }

            #pragma unroll
            for (int i = 0; i < EE; i++){
                u64 sg = splat2(g[i]);
                const ulonglong2* w = (const ulonglong2*)&sWG[i][0];
                ulonglong2 w0 = w[0], w1 = w[1];
                u64 w4 = ((const u64*)&sWG[i][0])[4];
                accH[0] = ffma2(sg, w0.x, accH[0]);
                accH[1] = ffma2(sg, w0.y, accH[1]);
                accH[2] = ffma2(sg, w1.x, accH[2]);
                accH[3] = ffma2(sg, w1.y, accH[3]);
                accH[4] = ffma2(sg, w4,   accH[4]);
            }

            #pragma unroll
            for (int p = 0; p < 5; p++){
                float c0, c1; unpack2(accH[p], c0, c1);
                float hc0 = tanhf_fast(c0);
                float hc1 = tanhf_fast(c1);
                float2 av = *(const float2*)(mya + 2*p);
                float Ra0 = av.x * r[2*p];
                float Ra1 = av.y * r[2*p+1];
                h[2*p]   = h[2*p]   + Ra0 * (hc0 - h[2*p]);
                h[2*p+1] = h[2*p+1] + Ra1 * (hc1 - h[2*p+1]);
            }

            // between halves: stage chunk c+1 into the idle buffer (safe: it was
            // last read in chunk c-1, all warps past that sync)
            if (half == 0 && c + 1 < TT/2){
                float* buf = sIn[(c + 1) & 1];
                #pragma unroll
                for (int k = 0; k < 5; k++){
                    float* d = &buf[sbase[k]];
                    *(float2*)(d)      = make_float2(vx[k].x, vx[k].y);
                    *(float2*)(d + 2)  = make_float2(vx[k].z, vx[k].w);
                    *(float2*)(d + 20) = make_float2(va[k].x, va[k].y);
                    *(float2*)(d + 22) = make_float2(va[k].z, va[k].w);
                }
            }
        }
        __syncthreads();
    }

    long b = b0 + tid;
    #pragma unroll
    for (int p = 0; p < 5; p++){
        float2 o; o.x = h[2*p]; o.y = h[2*p+1];
        *(float2*)(out + b*EE + 2*p) = o;
    }
}

extern "C" void kernel_launch(void* const* d_in, const int* in_sizes, int n_in,
                              void* d_out, int out_size)
{
    const float* X   = (const float*)d_in[0];
    const float* Aat = (const float*)d_in[1];
    const float* h0  = (const float*)d_in[2];

    augru_kernel<<<BB / NTH, NTH>>>(
        X, Aat, h0,
        (const float*)d_in[3],  (const float*)d_in[4],  (const float*)d_in[5],
        (const float*)d_in[6],  (const float*)d_in[7],
        (const float*)d_in[8],  (const float*)d_in[9],  (const float*)d_in[10],
        (const float*)d_in[11], (const float*)d_in[12],
        (const float*)d_in[13], (const float*)d_in[14], (const float*)d_in[15],
        (const float*)d_in[16], (const float*)d_in[17],
        (float*)d_out);
}

// round 16
// speedup vs baseline: 1.0823x; 1.0823x over previous
#include <cuda_runtime.h>

typedef unsigned long long u64;

#define TT 50
#define EE 10
#define BB 65536

__device__ __forceinline__ u64 ffma2(u64 a, u64 b, u64 c){
    u64 d; asm("fma.rn.f32x2 %0, %1, %2, %3;" : "=l"(d) : "l"(a), "l"(b), "l"(c)); return d;
}
__device__ __forceinline__ u64 splat2(float v){
    u64 r; asm("mov.b64 %0, {%1, %1};" : "=l"(r) : "f"(v)); return r;
}
__device__ __forceinline__ void unpack2(u64 v, float& lo, float& hi){
    asm("mov.b64 {%0, %1}, %2;" : "=f"(lo), "=f"(hi) : "l"(v));
}
__device__ __forceinline__ float sigmoidf_fast(float v){
    return __fdividef(1.0f, 1.0f + __expf(-v));
}
__device__ __forceinline__ float tanhf_fast(float v){
    return 1.0f - __fdividef(2.0f, __expf(2.0f * v) + 1.0f);
}

#define NTH 64
#define RSTRIDE 42   // floats per batch row: [0..19]=x(t0,t1), [20..39]=a(t0,t1), pad 2 (conflict-free LDS.64 reads)

__global__ void __launch_bounds__(NTH, 7) augru_kernel(
    const float* __restrict__ X, const float* __restrict__ Aat,
    const float* __restrict__ h0,
    const float* __restrict__ Wi_r, const float* __restrict__ bi_r,
    const float* __restrict__ Wh_r, const float* __restrict__ Ws_r, const float* __restrict__ bs_r,
    const float* __restrict__ Wi_z, const float* __restrict__ bi_z,
    const float* __restrict__ Wh_z, const float* __restrict__ Ws_z, const float* __restrict__ bs_z,
    const float* __restrict__ Wi_h, const float* __restrict__ bi_h,
    const float* __restrict__ Wh_h, const float* __restrict__ Wt_h, const float* __restrict__ bt_h,
    float* __restrict__ out)
{
    // Packed fused weights (co-consumed rows contiguous):
    //  sWX[i][0..9]=(Wi_r@Ws_r)[i], [10..19]=(Wi_z@Ws_z)[i], [20..29]=(Wi_h@Wt_h)[i]
    //  sWH[i][0..9]=(Wh_r@Ws_r)[i], [10..19]=(Wh_z@Ws_z)[i]
    //  sWG[i][0..9]=(Wh_h@Wt_h)[i]
    __shared__ __align__(16) float sWX[EE][32];
    __shared__ __align__(16) float sWH[EE][24];
    __shared__ __align__(16) float sWG[EE][16];
    __shared__ __align__(16) float sB[3][16];
    __shared__ float sH0[16];
    __shared__ __align__(16) float sIn[2][NTH * RSTRIDE];   // 2 x 10752 B

    {
        for (int idx = threadIdx.x; idx < EE * 32; idx += NTH){
            int i = idx >> 5, j = idx & 31;
            float v = 0.0f;
            if (j < 30){
                int m = j / 10, jj = j % 10;
                const float* a  = (m==0) ? Wi_r : (m==1) ? Wi_z : Wi_h;
                const float* b2 = (m==0) ? Ws_r : (m==1) ? Ws_z : Wt_h;
                #pragma unroll
                for (int k = 0; k < EE; k++) v = fmaf(a[i*EE + k], b2[k*EE + jj], v);
            }
            sWX[i][j] = v;
        }
        for (int idx = threadIdx.x; idx < EE * 24; idx += NTH){
            int i = idx / 24, j = idx % 24;
            float v = 0.0f;
            if (j < 20){
                int m = j / 10, jj = j % 10;
                const float* a  = (m==0) ? Wh_r : Wh_z;
                const float* b2 = (m==0) ? Ws_r : Ws_z;
                #pragma unroll
                for (int k = 0; k < EE; k++) v = fmaf(a[i*EE + k], b2[k*EE + jj], v);
            }
            sWH[i][j] = v;
        }
        for (int idx = threadIdx.x; idx < EE * 16; idx += NTH){
            int i = idx >> 4, j = idx & 15;
            float v = 0.0f;
            if (j < EE){
                #pragma unroll
                for (int k = 0; k < EE; k++) v = fmaf(Wh_h[i*EE + k], Wt_h[k*EE + j], v);
            }
            sWG[i][j] = v;
        }
        for (int idx = threadIdx.x; idx < 48; idx += NTH){
            int g = idx >> 4, j = idx & 15;
            float v = 0.0f;
            if (j < EE){
                const float* bi = (g==0) ? bi_r : (g==1) ? bi_z : bi_h;
                const float* bs = (g==0) ? bs_r : (g==1) ? bs_z : bt_h;
                const float* Wg = (g==0) ? Ws_r : (g==1) ? Ws_z : Wt_h;
                v = bs[j];
                #pragma unroll
                for (int k = 0; k < EE; k++) v = fmaf(bi[k], Wg[k*EE + j], v);
            }
            sB[g][j] = v;
        }
        if (threadIdx.x < 16) sH0[threadIdx.x] = (threadIdx.x < EE) ? h0[threadIdx.x] : 0.0f;
    }

    const int tid = threadIdx.x;
    const long b0 = (long)blockIdx.x * NTH;

    // 2-step chunk staging from [B][T][E]. Slot k: idx = tid+64k -> bb=idx/5, pp=idx%5.
    // Global float4 index for chunk c: (b0+bb)*125 + c*5 + pp  (always 16B-aligned).
    const float4* X4 = (const float4*)X;
    const float4* A4 = (const float4*)Aat;
    long gbase[5]; int sbase[5];
    #pragma unroll
    for (int k = 0; k < 5; k++){
        int idx = tid + NTH*k;
        int bb = idx / 5, pp = idx % 5;
        gbase[k] = (b0 + bb) * 125 + pp;
        sbase[k] = bb * RSTRIDE + 4*pp;
    }

    // stage chunk 0 (LDG -> STS immediately; short live ranges)
    {
        #pragma unroll
        for (int k = 0; k < 5; k++){
            float4 vx = X4[gbase[k]];
            float4 va = A4[gbase[k]];
            float* d = &sIn[0][sbase[k]];
            *(float2*)(d)      = make_float2(vx.x, vx.y);
            *(float2*)(d + 2)  = make_float2(vx.z, vx.w);
            *(float2*)(d + 20) = make_float2(va.x, va.y);
            *(float2*)(d + 22) = make_float2(va.z, va.w);
        }
    }
    __syncthreads();

    float h[EE];
    #pragma unroll
    for (int j = 0; j < EE; j++) h[j] = sH0[j];

    #pragma unroll 1
    for (int c = 0; c < TT/2; c++){
        // stage chunk c+1 into the idle buffer NOW (no register carry across compute).
        // buf[(c+1)&1] was last read in chunk c-1; the barrier at the end of c-1 protects it.
        if (c + 1 < TT/2){
            float* buf = sIn[(c + 1) & 1];
            #pragma unroll
            for (int k = 0; k < 5; k++){
                float4 vx = X4[gbase[k] + (c+1)*5];
                float4 va = A4[gbase[k] + (c+1)*5];
                float* d = &buf[sbase[k]];
                *(float2*)(d)      = make_float2(vx.x, vx.y);
                *(float2*)(d + 2)  = make_float2(vx.z, vx.w);
                *(float2*)(d + 20) = make_float2(va.x, va.y);
                *(float2*)(d + 22) = make_float2(va.z, va.w);
            }
        }

        const float* myrow = &sIn[c & 1][tid * RSTRIDE];

        #pragma unroll
        for (int half = 0; half < 2; half++){
            const float* myx = myrow + half*10;
            const float* mya = myrow + 20 + half*10;

            float x[EE];
            #pragma unroll
            for (int p = 0; p < 5; p++){
                float2 v = *(const float2*)(myx + 2*p);
                x[2*p] = v.x; x[2*p+1] = v.y;
            }

            u64 accR[5], accZ[5], accH[5];
            #pragma unroll
            for (int p = 0; p < 5; p++){
                accR[p] = *(const u64*)&sB[0][2*p];
                accZ[p] = *(const u64*)&sB[1][2*p];
                accH[p] = *(const u64*)&sB[2][2*p];
            }

            // x contributions: packed 32-float row feeds all three gates
            #pragma unroll
            for (int i = 0; i < EE; i++){
                u64 sx = splat2(x[i]);
                const ulonglong2* w = (const ulonglong2*)&sWX[i][0];
                ulonglong2 w0 = w[0], w1 = w[1], w2 = w[2], w3 = w[3];
                accR[0] = ffma2(sx, w0.x, accR[0]);
                accR[1] = ffma2(sx, w0.y, accR[1]);
                accR[2] = ffma2(sx, w1.x, accR[2]);
                accR[3] = ffma2(sx, w1.y, accR[3]);
                accR[4] = ffma2(sx, w2.x, accR[4]);
                accZ[0] = ffma2(sx, w2.y, accZ[0]);
                accZ[1] = ffma2(sx, w3.x, accZ[1]);
                accZ[2] = ffma2(sx, w3.y, accZ[2]);
                ulonglong2 w4 = w[4], w5 = w[5], w6 = w[6], w7 = w[7];
                accZ[3] = ffma2(sx, w4.x, accZ[3]);
                accZ[4] = ffma2(sx, w4.y, accZ[4]);
                accH[0] = ffma2(sx, w5.x, accH[0]);
                accH[1] = ffma2(sx, w5.y, accH[1]);
                accH[2] = ffma2(sx, w6.x, accH[2]);
                accH[3] = ffma2(sx, w6.y, accH[3]);
                accH[4] = ffma2(sx, w7.x, accH[4]);
            }
            // h contributions: packed 24-float row feeds r and z
            #pragma unroll
            for (int i = 0; i < EE; i++){
                u64 sh = splat2(h[i]);
                const ulonglong2* w = (const ulonglong2*)&sWH[i][0];
                ulonglong2 w0 = w[0], w1 = w[1];
                u64 w2x = ((const u64*)&sWH[i][0])[4];
                accR[0] = ffma2(sh, w0.x, accR[0]);
                accR[1] = ffma2(sh, w0.y, accR[1]);
                accR[2] = ffma2(sh, w1.x, accR[2]);
                accR[3] = ffma2(sh, w1.y, accR[3]);
                accR[4] = ffma2(sh, w2x,  accR[4]);
                ulonglong2 w2 = ((const ulonglong2*)&sWH[i][0])[2];
                ulonglong2 w3 = w[3], w4 = w[4];
                accZ[0] = ffma2(sh, w2.y, accZ[0]);
                accZ[1] = ffma2(sh, w3.x, accZ[1]);
                accZ[2] = ffma2(sh, w3.y, accZ[2]);
                accZ[3] = ffma2(sh, w4.x, accZ[3]);
                accZ[4] = ffma2(sh, w4.y, accZ[4]);
            }

            float r[EE], g[EE];
            #pragma unroll
            for (int p = 0; p < 5; p++){
                float r0, r1; unpack2(accR[p], r0, r1);
                r[2*p]   = sigmoidf_fast(r0);
                r[2*p+1] = sigmoidf_fast(r1);
                float z0, z1; unpack2(accZ[p], z0, z1);
                g[2*p]   = h[2*p]   * sigmoidf_fast(z0);
                g[2*p+1] = h[2*p+1] * sigmoidf_fast(z1);
            }

            #pragma unroll
            for (int i = 0; i < EE; i++){
                u64 sg = splat2(g[i]);
                const ulonglong2* w = (const ulonglong2*)&sWG[i][0];
                ulonglong2 w0 = w[0], w1 = w[1];
                u64 w4 = ((const u64*)&sWG[i][0])[4];
                accH[0] = ffma2(sg, w0.x, accH[0]);
                accH[1] = ffma2(sg, w0.y, accH[1]);
                accH[2] = ffma2(sg, w1.x, accH[2]);
                accH[3] = ffma2(sg, w1.y, accH[3]);
                accH[4] = ffma2(sg, w4,   accH[4]);
            }

            #pragma unroll
            for (int p = 0; p < 5; p++){
                float c0, c1; unpack2(accH[p], c0, c1);
                float hc0 = tanhf_fast(c0);
                float hc1 = tanhf_fast(c1);
                float2 av = *(const float2*)(mya + 2*p);
                float Ra0 = av.x * r[2*p];
                float Ra1 = av.y * r[2*p+1];
                h[2*p]   = h[2*p]   + Ra0 * (hc0 - h[2*p]);
                h[2*p+1] = h[2*p+1] + Ra1 * (hc1 - h[2*p+1]);
            }
        }
        __syncthreads();
    }

    long b = b0 + tid;
    #pragma unroll
    for (int p = 0; p < 5; p++){
        float2 o; o.x = h[2*p]; o.y = h[2*p+1];
        *(float2*)(out + b*EE + 2*p) = o;
    }
}

extern "C" void kernel_launch(void* const* d_in, const int* in_sizes, int n_in,
                              void* d_out, int out_size)
{
    const float* X   = (const float*)d_in[0];
    const float* Aat = (const float*)d_in[1];
    const float* h0  = (const float*)d_in[2];

    augru_kernel<<<BB / NTH, NTH>>>(
        X, Aat, h0,
        (const float*)d_in[3],  (const float*)d_in[4],  (const float*)d_in[5],
        (const float*)d_in[6],  (const float*)d_in[7],
        (const float*)d_in[8],  (const float*)d_in[9],  (const float*)d_in[10],
        (const float*)d_in[11], (const float*)d_in[12],
        (const float*)d_in[13], (const float*)d_in[14], (const float*)d_in[15],
        (const float*)d_in[16], (const float*)d_in[17],
        (float*)d_out);
}